// round 9
// baseline (speedup 1.0000x reference)
#include <cuda_runtime.h>
#include <math.h>
#include <stdint.h>

#define BZ    8
#define IM    128
#define HW    (IM * IM)        // 16384
#define CIN   3

#define NPROD       256        // 16 colgroups * 2 o-halves * 8 batches
#define PROD_PER_B  32
#define NCONS       (129 * BZ) // 1032

// E[b][o][w] = leakyrelu(W @ S);  handshake counters (self-resetting).
__device__ float g_E[BZ * IM * IM];
__device__ int   g_prod[BZ];
__device__ int   g_cons[BZ];

__global__ void __launch_bounds__(256) fused_kernel(const float* __restrict__ x,
                                                    const float* __restrict__ conv_w,
                                                    float* __restrict__ out) {
    // 46.3 KB static smem (only producers use it; uniform per-block reservation).
    __shared__ float4 sW4[32 * 64];                 // swizzled half-W  (32 KB)
    __shared__ float  sRe[8][IM], sIm[8][IM], sS[8][IM];   // 12 KB
    __shared__ float  t128c[IM], t128s[IM], t32c[32], t32s[32];

    const int bid = blockIdx.x;
    const int tid = threadIdx.x;

    if (bid < NPROD) {
        // ================= PRODUCER: DFT + GEMM for 8 columns ================
        const int b    = bid >> 5;
        const int pb   = bid & 31;
        const int og   = pb & 1;          // o-half: rows [og*64, og*64+64)
        const int cg   = pb >> 1;         // column group: w in [cg*8, cg*8+8)
        const int wl   = tid >> 5;        // warp -> local column (0..7)
        const int lane = tid & 31;

        // Stage half of W (2048 float4, 8 per thread), swizzled store.
        const float4* W4 = (const float4*)conv_w;
#pragma unroll
        for (int it = 0; it < 8; it++) {
            int idx = tid + 256 * it;                 // 0..2047
            int op = idx >> 5, j = idx & 31;          // o' in [0,64), j in [0,32)
            sW4[j * 64 + (j ^ op)] = W4[(og * 64 + op) * 32 + j];
        }

        // Load 8 columns (both channels): 512 float4.
        const float* xb = x + (size_t)b * CIN * HW;
        for (int idx = tid; idx < 512; idx += 256) {
            int ch = idx >> 8, rem = idx & 255;
            int h = rem >> 1, half = rem & 1;         // half: which float4 of 8 cols
            float4 v = ((const float4*)(xb + (size_t)ch * HW))[h * (IM / 4) + 2 * cg + half];
            float (*dst)[IM] = ch ? sIm : sRe;
            dst[half * 4 + 0][h] = v.x; dst[half * 4 + 1][h] = v.y;
            dst[half * 4 + 2][h] = v.z; dst[half * 4 + 3][h] = v.w;
        }

        // Twiddle tables (exact).
        if (tid < 160) {
            float s, c;
            if (tid < 128) {
                sincosf(-6.283185307179586f * (float)tid * (1.0f / 128.0f), &s, &c);
                t128c[tid] = c; t128s[tid] = s;
            } else {
                int k = tid - 128;
                sincosf(-6.283185307179586f * (float)k * (1.0f / 32.0f), &s, &c);
                t32c[k] = c; t32s[k] = s;
            }
        }
        __syncthreads();

        // Radix-4 DFT: warp wl handles its column; lane -> outputs lane,+32,+64,+96.
        float A0r = 0, A0i = 0, A1r = 0, A1i = 0, A2r = 0, A2i = 0, A3r = 0, A3i = 0;
        const float4* r4 = (const float4*)sRe[wl];
        const float4* m4 = (const float4*)sIm[wl];

#pragma unroll
        for (int t = 0; t < 32; t++) {
            int   k = (lane * t) & 31;
            float c = t32c[k], s = t32s[k];
            float4 xr = r4[t];
            float4 xm = m4[t];
            A0r = fmaf(xr.x, c, A0r); A0r = fmaf(-xm.x, s, A0r);
            A0i = fmaf(xr.x, s, A0i); A0i = fmaf( xm.x, c, A0i);
            A1r = fmaf(xr.y, c, A1r); A1r = fmaf(-xm.y, s, A1r);
            A1i = fmaf(xr.y, s, A1i); A1i = fmaf( xm.y, c, A1i);
            A2r = fmaf(xr.z, c, A2r); A2r = fmaf(-xm.z, s, A2r);
            A2i = fmaf(xr.z, s, A2i); A2i = fmaf( xm.z, c, A2i);
            A3r = fmaf(xr.w, c, A3r); A3r = fmaf(-xm.w, s, A3r);
            A3i = fmaf(xr.w, s, A3i); A3i = fmaf( xm.w, c, A3i);
        }

        float cw = t128c[lane],             sw = t128s[lane];
        float c2 = t128c[(2 * lane) & 127], s2 = t128s[(2 * lane) & 127];
        float c3 = t128c[(3 * lane) & 127], s3 = t128s[(3 * lane) & 127];

        float T0r = A0r,                 T0i = A0i;
        float T1r = cw * A1r - sw * A1i, T1i = cw * A1i + sw * A1r;
        float T2r = c2 * A2r - s2 * A2i, T2i = c2 * A2i + s2 * A2r;
        float T3r = c3 * A3r - s3 * A3i, T3i = c3 * A3i + s3 * A3r;

        float Er = T0r + T2r, Ei = T0i + T2i;
        float Fr = T1r + T3r, Fi = T1i + T3i;
        float Gr = T0r - T2r, Gi = T0i - T2i;
        float Hr = T1r - T3r, Hi = T1i - T3i;

        float m0r = Er + Fr, m0i = Ei + Fi;
        float m2r = Er - Fr, m2i = Ei - Fi;
        float m1r = Gr + Hi, m1i = Gi - Hr;
        float m3r = Gr - Hi, m3i = Gi + Hr;

        const float inv = 1.0f / 128.0f;
        sS[wl][lane     ] = sqrtf(m0r * m0r + m0i * m0i) * inv;
        sS[wl][lane + 32] = sqrtf(m1r * m1r + m1i * m1i) * inv;
        sS[wl][lane + 64] = sqrtf(m2r * m2r + m2i * m2i) * inv;
        sS[wl][lane + 96] = sqrtf(m3r * m3r + m3i * m3i) * inv;
        __syncthreads();

        // GEMM: thread -> (o' = tid&63, local cols 2q, 2q+1 with q = tid>>6).
        const int op = tid & 63;
        const int q  = tid >> 6;
        float a0 = 0, a1 = 0;
        const float4* qa = (const float4*)sS[2 * q];
        const float4* qb = (const float4*)sS[2 * q + 1];

#pragma unroll 8
        for (int i4 = 0; i4 < 32; i4++) {
            float4 wv = sW4[i4 * 64 + (i4 ^ op)];      // conflict-free
            float4 va = qa[i4], vb = qb[i4];
            a0 = fmaf(wv.x, va.x, a0); a0 = fmaf(wv.y, va.y, a0);
            a0 = fmaf(wv.z, va.z, a0); a0 = fmaf(wv.w, va.w, a0);
            a1 = fmaf(wv.x, vb.x, a1); a1 = fmaf(wv.y, vb.y, a1);
            a1 = fmaf(wv.z, vb.z, a1); a1 = fmaf(wv.w, vb.w, a1);
        }

        float2 e;
        e.x = (a0 >= 0.0f) ? a0 : 0.2f * a0;
        e.y = (a1 >= 0.0f) ? a1 : 0.2f * a1;
        *(float2*)(g_E + (size_t)(b * IM + og * 64 + op) * IM + cg * 8 + 2 * q) = e;

        // Publish: make E visible gpu-wide, then bump the batch counter.
        __threadfence();
        __syncthreads();
        if (tid == 0) atomicAdd(&g_prod[b], 1);

    } else {
        // ================= CONSUMER: broadcast one (b,o) row =================
        const int cid = bid - NPROD;
        const int b   = cid / 129;
        const int o   = cid - b * 129;

        if (o == IM) {
            // Independent passthrough of x channel 2 — no wait needed.
            float4*       d4  = (float4*)(out + (size_t)(b * (IM + 1) + IM) * HW);
            const float4* src = (const float4*)(x + (size_t)b * CIN * HW + 2 * HW);
#pragma unroll
            for (int j = tid; j < HW / 4; j += 256) d4[j] = src[j];
            return;
        }

        // Wait for batch b's producers.
        if (tid == 0) {
            volatile int* p = g_prod + b;
            while (*p < PROD_PER_B) __nanosleep(64);
        }
        __syncthreads();
        __threadfence();                               // acquire ordering

        const float4* e4 = (const float4*)(g_E + (size_t)(b * IM + o) * IM);
        float4 v = __ldcg(e4 + (tid & 31));            // L2 read, skip L1
        float4* out4 = (float4*)(out + (size_t)(b * (IM + 1) + o) * HW);
        const int w4 = tid & 31;
        const int h0 = tid >> 5;                       // 0..7
#pragma unroll
        for (int h = h0; h < IM; h += 8) out4[h * (IM / 4) + w4] = v;

        // Reset protocol: 128th consumer of batch b zeroes both counters
        // (safe: every consumer increments only after its poll succeeded).
        __syncthreads();
        if (tid == 0) {
            int old = atomicAdd(&g_cons[b], 1);
            if (old == IM - 1) {
                *(volatile int*)&g_prod[b] = 0;
                *(volatile int*)&g_cons[b] = 0;
            }
        }
    }
}

// ---------------------------------------------------------------------------
extern "C" void kernel_launch(void* const* d_in, const int* in_sizes, int n_in,
                              void* d_out, int out_size) {
    const float* x      = (const float*)d_in[0];
    const float* conv_w = (const float*)d_in[2];
    float*       out    = (float*)d_out;

    fused_kernel<<<NPROD + NCONS, 256>>>(x, conv_w, out);
}